// round 13
// baseline (speedup 1.0000x reference)
#include <cuda_runtime.h>
#include <cstdint>

#define BB 8
#define LL 2048
#define DD 64
#define TQ 64
#define TK 64

// index lists for mask compaction (device globals: allocation-free scratch)
__device__ int g_qlist[BB][LL];
__device__ int g_klist[BB][LL];
__device__ int g_qcnt[BB];
__device__ int g_kcnt[BB];

// ---------------------------------------------------------------------------
// Kernel 1: deterministic per-batch compaction of valid q/k indices.
// ---------------------------------------------------------------------------
__global__ void compact_kernel(const int* __restrict__ qm, const int* __restrict__ km) {
    int b = blockIdx.x;
    int tid = threadIdx.x;
    __shared__ int cnt[256];

    // ---- q mask ----
    {
        const int* m = qm + (size_t)b * LL;
        int base = tid * 8;
        int c = 0;
#pragma unroll
        for (int k = 0; k < 8; ++k) c += (m[base + k] != 0);
        cnt[tid] = c;
        __syncthreads();
        if (tid == 0) {
            int run = 0;
            for (int t = 0; t < 256; ++t) { int v = cnt[t]; cnt[t] = run; run += v; }
            g_qcnt[b] = run;
        }
        __syncthreads();
        int pos = cnt[tid];
#pragma unroll
        for (int k = 0; k < 8; ++k)
            if (m[base + k] != 0) g_qlist[b][pos++] = base + k;
        __syncthreads();
    }
    // ---- k mask ----
    {
        const int* m = km + (size_t)b * LL;
        int base = tid * 8;
        int c = 0;
#pragma unroll
        for (int k = 0; k < 8; ++k) c += (m[base + k] != 0);
        cnt[tid] = c;
        __syncthreads();
        if (tid == 0) {
            int run = 0;
            for (int t = 0; t < 256; ++t) { int v = cnt[t]; cnt[t] = run; run += v; }
            g_kcnt[b] = run;
        }
        __syncthreads();
        int pos = cnt[tid];
#pragma unroll
        for (int k = 0; k < 8; ++k)
            if (m[base + k] != 0) g_klist[b][pos++] = base + k;
    }
}

// ---------------------------------------------------------------------------
// Kernel 2: fused attention over compacted indices.
// 128 threads (16 tx x 8 ty), 8x4 micro-tiles, TQ=TK=64.
// Swizzle: element (row, float4-group g) at row*64 + ((g ^ (row>>2)) & 15)*4.
//   - phase-A K loads (rows 4*tx+j): chunk = g ^ tx -> conflict-free per phase
//   - phase-B V loads (g = tx):      chunk = tx ^ (row>>2) -> conflict-free
//   - Q/P same-address loads broadcast; all stores conflict-free.
// __launch_bounds__(128,3): 12 warps/SM, 3 x 64KB smem = 192KB <= 228KB.
// ---------------------------------------------------------------------------
__device__ __forceinline__ int swz(int row, int g) {
    return row * 64 + (((g ^ (row >> 2)) & 15) << 2);
}

extern __shared__ float smem[];

__global__ void __launch_bounds__(128, 3)
attn_kernel(const float* __restrict__ Q, const float* __restrict__ K,
            const float* __restrict__ V, float* __restrict__ out) {
    int b  = blockIdx.y;
    int nq = g_qcnt[b];
    int nk = g_kcnt[b];
    int q0 = blockIdx.x * TQ;
    if (q0 >= nq) return;   // early exit before any barrier

    float* Qs = smem;            // 4096 floats
    float* Ks = smem + 4096;     // 4096
    float* Vs = smem + 8192;     // 4096
    float* Ps = smem + 12288;    // 4096

    int tid = threadIdx.x;
    int tx = tid & 15;           // k-col / d-col group (0..15)
    int ty = tid >> 4;           // q-row group (0..7), 8 rows each

    // ---- load Q tile (gathered, pre-scaled by 1/sqrt(D)=0.125) ----
    {
        int g = tid & 15;
        int r = tid >> 4;        // 0..7
#pragma unroll
        for (int pass = 0; pass < 8; ++pass) {
            int row = r + pass * 8;
            int qi = q0 + row;
            float4 v = make_float4(0.f, 0.f, 0.f, 0.f);
            if (qi < nq) {
                int src = g_qlist[b][qi];
                v = *(const float4*)&Q[((size_t)b * LL + src) * DD + g * 4];
                v.x *= 0.125f; v.y *= 0.125f; v.z *= 0.125f; v.w *= 0.125f;
            }
            *(float4*)&Qs[swz(row, g)] = v;
        }
    }
    __syncthreads();

    float acc[8][4];   // O accumulator: q rows ty*8+i, d cols tx*4..
    float rs[8];       // partial row sums over this thread's 4 k columns
#pragma unroll
    for (int i = 0; i < 8; ++i) {
        rs[i] = 0.f;
#pragma unroll
        for (int j = 0; j < 4; ++j) acc[i][j] = 0.f;
    }

    int ntiles = (nk + TK - 1) / TK;
    for (int t = 0; t < ntiles; ++t) {
        int k0 = t * TK;

        // ---- load K and V tiles (gathered) ----
        {
            int g = tid & 15;
            int r = tid >> 4;
#pragma unroll
            for (int pass = 0; pass < 8; ++pass) {
                int row = r + pass * 8;
                int ki = k0 + row;
                float4 kv = make_float4(0.f, 0.f, 0.f, 0.f);
                float4 vv = make_float4(0.f, 0.f, 0.f, 0.f);
                if (ki < nk) {
                    int src = g_klist[b][ki];
                    const float* kp = &K[((size_t)b * LL + src) * DD + g * 4];
                    const float* vp = &V[((size_t)b * LL + src) * DD + g * 4];
                    kv = *(const float4*)kp;
                    vv = *(const float4*)vp;
                }
                *(float4*)&Ks[swz(row, g)] = kv;
                *(float4*)&Vs[swz(row, g)] = vv;
            }
        }
        __syncthreads();

        // ---- phase A: S = Qs @ Ks^T (8q x 4k micro-tile) ----
        float s[8][4];
#pragma unroll
        for (int i = 0; i < 8; ++i)
#pragma unroll
            for (int j = 0; j < 4; ++j) s[i][j] = 0.f;

#pragma unroll
        for (int dg = 0; dg < 16; ++dg) {
            float4 kv[4];
#pragma unroll
            for (int j = 0; j < 4; ++j) kv[j] = *(float4*)&Ks[swz(tx * 4 + j, dg)];
#pragma unroll
            for (int i = 0; i < 8; ++i) {
                float4 qv = *(float4*)&Qs[swz(ty * 8 + i, dg)];
#pragma unroll
                for (int j = 0; j < 4; ++j)
                    s[i][j] += qv.x * kv[j].x + qv.y * kv[j].y +
                               qv.z * kv[j].z + qv.w * kv[j].w;
            }
        }

        // exp (compacted k all valid; only tile-padding columns masked),
        // accumulate row sums, write P tile
#pragma unroll
        for (int i = 0; i < 8; ++i) {
            float pv[4];
#pragma unroll
            for (int j = 0; j < 4; ++j) {
                int kc = k0 + tx * 4 + j;
                float e = (kc < nk) ? __expf(s[i][j]) : 0.0f;
                pv[j] = e;
                rs[i] += e;
            }
            *(float4*)&Ps[swz(ty * 8 + i, tx)] =
                make_float4(pv[0], pv[1], pv[2], pv[3]);
        }
        __syncthreads();

        // ---- phase B: O += P @ V (8q x 4d micro-tile) ----
#pragma unroll
        for (int kg = 0; kg < 16; ++kg) {
            float4 v0 = *(float4*)&Vs[swz(kg * 4 + 0, tx)];
            float4 v1 = *(float4*)&Vs[swz(kg * 4 + 1, tx)];
            float4 v2 = *(float4*)&Vs[swz(kg * 4 + 2, tx)];
            float4 v3 = *(float4*)&Vs[swz(kg * 4 + 3, tx)];
#pragma unroll
            for (int i = 0; i < 8; ++i) {
                float4 p = *(float4*)&Ps[swz(ty * 8 + i, kg)];
                acc[i][0] += p.x * v0.x + p.y * v1.x + p.z * v2.x + p.w * v3.x;
                acc[i][1] += p.x * v0.y + p.y * v1.y + p.z * v2.y + p.w * v3.y;
                acc[i][2] += p.x * v0.z + p.y * v1.z + p.z * v2.z + p.w * v3.z;
                acc[i][3] += p.x * v0.w + p.y * v1.w + p.z * v2.w + p.w * v3.w;
            }
        }
        __syncthreads();
    }

    // ---- reduce row sums across the 16 tx threads (deterministic order) ----
    float* RS = Ks;   // reuse: [qr][tx] partials, 64*16 floats
#pragma unroll
    for (int i = 0; i < 8; ++i)
        RS[(ty * 8 + i) * 16 + tx] = rs[i];
    __syncthreads();

    float* Rtot = Vs; // reuse: 64 floats
    if (tid < 64) {
        float tsum = 0.f;
#pragma unroll
        for (int u = 0; u < 16; ++u) tsum += RS[tid * 16 + u];
        Rtot[tid] = fmaxf(tsum, 1.0f);
    }
    __syncthreads();

    // ---- scale & scatter output rows back to original q positions ----
#pragma unroll
    for (int i = 0; i < 8; ++i) {
        int qr = ty * 8 + i;
        int qi = q0 + qr;
        if (qi < nq) {
            float inv = 1.0f / Rtot[qr];
            int src = g_qlist[b][qi];
            float4 o = make_float4(acc[i][0] * inv, acc[i][1] * inv,
                                   acc[i][2] * inv, acc[i][3] * inv);
            *(float4*)&out[((size_t)b * LL + src) * DD + tx * 4] = o;
        }
    }
}

// ---------------------------------------------------------------------------
extern "C" void kernel_launch(void* const* d_in, const int* in_sizes, int n_in,
                              void* d_out, int out_size) {
    const float* Q  = (const float*)d_in[0];
    const float* K  = (const float*)d_in[1];
    const float* V  = (const float*)d_in[2];
    const int*   qm = (const int*)d_in[3];
    const int*   km = (const int*)d_in[4];
    float* out = (float*)d_out;

    // 64 KB dynamic smem (> 48 KB default) — idempotent host-side config
    cudaFuncSetAttribute(attn_kernel,
                         cudaFuncAttributeMaxDynamicSharedMemorySize, 65536);

    // zero-fill output: invalid q rows stay exactly 0
    cudaMemsetAsync(out, 0, (size_t)out_size * sizeof(float));

    compact_kernel<<<BB, 256>>>(qm, km);

    dim3 grid(LL / TQ, BB);   // 32 x 8; ~half exit immediately (q compaction)
    attn_kernel<<<grid, 128, 65536>>>(Q, K, V, out);
}

// round 14
// speedup vs baseline: 2.1655x; 2.1655x over previous
#include <cuda_runtime.h>
#include <cstdint>

#define BB 8
#define LL 2048
#define DD 64
#define TQ 64
#define TK 64
#define NSPLIT 2

// index lists for mask compaction (device globals: allocation-free scratch)
__device__ int g_qlist[BB][LL];
__device__ int g_klist[BB][LL];
__device__ int g_qcnt[BB];
__device__ int g_kcnt[BB];

// split-K partial buffers (unnormalized O and row sums), indexed by compacted q
__device__ float g_Opart[NSPLIT][BB][LL][DD];   // ~16.8 MB static scratch
__device__ float g_rspart[NSPLIT][BB][LL];

// ---------------------------------------------------------------------------
// Kernel 1: deterministic per-batch compaction of valid q/k indices.
// ---------------------------------------------------------------------------
__global__ void compact_kernel(const int* __restrict__ qm, const int* __restrict__ km) {
    int b = blockIdx.x;
    int tid = threadIdx.x;
    __shared__ int cnt[256];

    // ---- q mask ----
    {
        const int* m = qm + (size_t)b * LL;
        int base = tid * 8;
        int c = 0;
#pragma unroll
        for (int k = 0; k < 8; ++k) c += (m[base + k] != 0);
        cnt[tid] = c;
        __syncthreads();
        if (tid == 0) {
            int run = 0;
            for (int t = 0; t < 256; ++t) { int v = cnt[t]; cnt[t] = run; run += v; }
            g_qcnt[b] = run;
        }
        __syncthreads();
        int pos = cnt[tid];
#pragma unroll
        for (int k = 0; k < 8; ++k)
            if (m[base + k] != 0) g_qlist[b][pos++] = base + k;
        __syncthreads();
    }
    // ---- k mask ----
    {
        const int* m = km + (size_t)b * LL;
        int base = tid * 8;
        int c = 0;
#pragma unroll
        for (int k = 0; k < 8; ++k) c += (m[base + k] != 0);
        cnt[tid] = c;
        __syncthreads();
        if (tid == 0) {
            int run = 0;
            for (int t = 0; t < 256; ++t) { int v = cnt[t]; cnt[t] = run; run += v; }
            g_kcnt[b] = run;
        }
        __syncthreads();
        int pos = cnt[tid];
#pragma unroll
        for (int k = 0; k < 8; ++k)
            if (m[base + k] != 0) g_klist[b][pos++] = base + k;
    }
}

// ---------------------------------------------------------------------------
// Kernel 2: fused attention over compacted indices, split-K over k tiles.
// 256 threads (16 tx x 16 ty), 4x4 micro-tiles, TQ=TK=64.
// blockIdx.z = split id; each split covers half the k tiles and emits
// unnormalized partial O rows + partial row sums (deterministic fixed split).
// Swizzle: element (row, float4-group g) at row*64 + ((g ^ (row>>2)) & 15)*4.
// All LDS/STS patterns conflict-free per 8-lane phase (K: g^tx distinct,
// V: tx^kg distinct, P store: tx^ty distinct, Q loads broadcast).
// __launch_bounds__(256,2): regs capped at 128 -> 2 CTAs/SM possible,
// smem 64KB x 2 = 128KB <= 228KB carveout.
// ---------------------------------------------------------------------------
__device__ __forceinline__ int swz(int row, int g) {
    return row * 64 + (((g ^ (row >> 2)) & 15) << 2);
}

extern __shared__ float smem[];

__global__ void __launch_bounds__(256, 2)
attn_kernel(const float* __restrict__ Q, const float* __restrict__ K,
            const float* __restrict__ V) {
    int b  = blockIdx.y;
    int sp = blockIdx.z;
    int nq = g_qcnt[b];
    int nk = g_kcnt[b];
    int q0 = blockIdx.x * TQ;
    if (q0 >= nq) return;   // early exit before any barrier

    float* Qs = smem;            // 4096 floats
    float* Ks = smem + 4096;     // 4096
    float* Vs = smem + 8192;     // 4096
    float* Ps = smem + 12288;    // 4096

    int tid = threadIdx.x;
    int tx = tid & 15;           // k / d micro-tile column group
    int ty = tid >> 4;           // q micro-tile row group

    // ---- load Q tile (gathered, pre-scaled by 1/sqrt(D)=0.125) ----
    {
        int g = tid & 15;
        int r = tid >> 4;
#pragma unroll
        for (int pass = 0; pass < 4; ++pass) {
            int row = r + pass * 16;
            int qi = q0 + row;
            float4 v = make_float4(0.f, 0.f, 0.f, 0.f);
            if (qi < nq) {
                int src = g_qlist[b][qi];
                v = *(const float4*)&Q[((size_t)b * LL + src) * DD + g * 4];
                v.x *= 0.125f; v.y *= 0.125f; v.z *= 0.125f; v.w *= 0.125f;
            }
            *(float4*)&Qs[swz(row, g)] = v;
        }
    }
    __syncthreads();

    float acc[4][4];   // O accumulator: q rows ty*4+i, d cols tx*4+j
    float rs[4];       // partial row sums over this thread's k columns
#pragma unroll
    for (int i = 0; i < 4; ++i) {
        rs[i] = 0.f;
#pragma unroll
        for (int j = 0; j < 4; ++j) acc[i][j] = 0.f;
    }

    int ntiles = (nk + TK - 1) / TK;
    int half   = (ntiles + 1) >> 1;
    int tbeg   = sp * half;
    int tend   = (sp == 0) ? half : ntiles;
    if (tend > ntiles) tend = ntiles;

    for (int t = tbeg; t < tend; ++t) {
        int k0 = t * TK;

        // ---- load K and V tiles (gathered) ----
        {
            int g = tid & 15;
            int r = tid >> 4;
#pragma unroll
            for (int pass = 0; pass < 4; ++pass) {
                int row = r + pass * 16;
                int ki = k0 + row;
                float4 kv = make_float4(0.f, 0.f, 0.f, 0.f);
                float4 vv = make_float4(0.f, 0.f, 0.f, 0.f);
                if (ki < nk) {
                    int src = g_klist[b][ki];
                    const float* kp = &K[((size_t)b * LL + src) * DD + g * 4];
                    const float* vp = &V[((size_t)b * LL + src) * DD + g * 4];
                    kv = *(const float4*)kp;
                    vv = *(const float4*)vp;
                }
                *(float4*)&Ks[swz(row, g)] = kv;
                *(float4*)&Vs[swz(row, g)] = vv;
            }
        }
        __syncthreads();

        // ---- phase A: S = Qs @ Ks^T (4x4 micro-tile) ----
        float s[4][4];
#pragma unroll
        for (int i = 0; i < 4; ++i)
#pragma unroll
            for (int j = 0; j < 4; ++j) s[i][j] = 0.f;

#pragma unroll
        for (int dg = 0; dg < 16; ++dg) {
            float4 qv[4], kv[4];
#pragma unroll
            for (int i = 0; i < 4; ++i) qv[i] = *(float4*)&Qs[swz(ty * 4 + i, dg)];
#pragma unroll
            for (int j = 0; j < 4; ++j) kv[j] = *(float4*)&Ks[swz(tx * 4 + j, dg)];
#pragma unroll
            for (int i = 0; i < 4; ++i)
#pragma unroll
                for (int j = 0; j < 4; ++j)
                    s[i][j] += qv[i].x * kv[j].x + qv[i].y * kv[j].y +
                               qv[i].z * kv[j].z + qv[i].w * kv[j].w;
        }

        // exp (compacted k all valid; only tile-padding columns masked),
        // accumulate row sums, write P tile
#pragma unroll
        for (int i = 0; i < 4; ++i) {
            float pv[4];
#pragma unroll
            for (int j = 0; j < 4; ++j) {
                int kc = k0 + tx * 4 + j;
                float e = (kc < nk) ? __expf(s[i][j]) : 0.0f;
                pv[j] = e;
                rs[i] += e;
            }
            *(float4*)&Ps[swz(ty * 4 + i, tx)] =
                make_float4(pv[0], pv[1], pv[2], pv[3]);
        }
        __syncthreads();

        // ---- phase B: O += P @ V (4x4 micro-tile over q x d) ----
#pragma unroll
        for (int kg = 0; kg < 16; ++kg) {
            float4 p[4];
#pragma unroll
            for (int i = 0; i < 4; ++i) p[i] = *(float4*)&Ps[swz(ty * 4 + i, kg)];
            float4 v0 = *(float4*)&Vs[swz(kg * 4 + 0, tx)];
            float4 v1 = *(float4*)&Vs[swz(kg * 4 + 1, tx)];
            float4 v2 = *(float4*)&Vs[swz(kg * 4 + 2, tx)];
            float4 v3 = *(float4*)&Vs[swz(kg * 4 + 3, tx)];
#pragma unroll
            for (int i = 0; i < 4; ++i) {
                acc[i][0] += p[i].x * v0.x + p[i].y * v1.x + p[i].z * v2.x + p[i].w * v3.x;
                acc[i][1] += p[i].x * v0.y + p[i].y * v1.y + p[i].z * v2.y + p[i].w * v3.y;
                acc[i][2] += p[i].x * v0.z + p[i].y * v1.z + p[i].z * v2.z + p[i].w * v3.z;
                acc[i][3] += p[i].x * v0.w + p[i].y * v1.w + p[i].z * v2.w + p[i].w * v3.w;
            }
        }
        __syncthreads();
    }

    // ---- reduce row sums across the 16 tx threads (deterministic order) ----
    float* RS = Ks;   // reuse: [qr][tx] partials, 64*16 floats
#pragma unroll
    for (int i = 0; i < 4; ++i)
        RS[(ty * 4 + i) * 16 + tx] = rs[i];
    __syncthreads();

    if (tid < 64) {
        int qi = q0 + tid;
        if (qi < nq) {
            float tsum = 0.f;
#pragma unroll
            for (int u = 0; u < 16; ++u) tsum += RS[tid * 16 + u];
            g_rspart[sp][b][qi] = tsum;   // NOT clamped; clamp happens in combine
        }
    }

    // ---- write unnormalized O partials at compacted positions ----
#pragma unroll
    for (int i = 0; i < 4; ++i) {
        int qi = q0 + ty * 4 + i;
        if (qi < nq) {
            *(float4*)&g_Opart[sp][b][qi][tx * 4] =
                make_float4(acc[i][0], acc[i][1], acc[i][2], acc[i][3]);
        }
    }
}

// ---------------------------------------------------------------------------
// Kernel 3: combine splits, clamp rowsum, normalize, scatter to output.
// 256 threads = 4 q rows x 64 d. Grid (LL/4, BB).
// ---------------------------------------------------------------------------
__global__ void combine_kernel(float* __restrict__ out) {
    int b  = blockIdx.y;
    int nq = g_qcnt[b];
    int qi = blockIdx.x * 4 + (threadIdx.x >> 6);
    int d  = threadIdx.x & 63;
    if (qi >= nq) return;
    float rs = fmaxf(g_rspart[0][b][qi] + g_rspart[1][b][qi], 1.0f);
    float o  = (g_Opart[0][b][qi][d] + g_Opart[1][b][qi][d]) / rs;
    int src  = g_qlist[b][qi];
    out[((size_t)b * LL + src) * DD + d] = o;
}

// ---------------------------------------------------------------------------
extern "C" void kernel_launch(void* const* d_in, const int* in_sizes, int n_in,
                              void* d_out, int out_size) {
    const float* Q  = (const float*)d_in[0];
    const float* K  = (const float*)d_in[1];
    const float* V  = (const float*)d_in[2];
    const int*   qm = (const int*)d_in[3];
    const int*   km = (const int*)d_in[4];
    float* out = (float*)d_out;

    // 64 KB dynamic smem (> 48 KB default) — idempotent host-side config
    cudaFuncSetAttribute(attn_kernel,
                         cudaFuncAttributeMaxDynamicSharedMemorySize, 65536);

    // zero-fill output: invalid q rows stay exactly 0
    cudaMemsetAsync(out, 0, (size_t)out_size * sizeof(float));

    compact_kernel<<<BB, 256>>>(qm, km);

    dim3 grid(LL / TQ, BB, NSPLIT);   // 32 x 8 x 2; ~half exit early (q compaction)
    attn_kernel<<<grid, 256, 65536>>>(Q, K, V);

    dim3 cgrid(LL / 4, BB);
    combine_kernel<<<cgrid, 256>>>(out);
}